// round 16
// baseline (speedup 1.0000x reference)
#include <cuda_runtime.h>
#include <cstdint>

// SpatialGradientLoss3D = mean |sobel3d(pred - target)| over 3 axes.
// R14: R13 pipeline + 2 output rows per thread (TH=16, warp w -> rows
// 2w,2w+1 from 4 row-reads instead of 6 for 2) and pend-style z-state
// (2-deep S history + pend accumulators; same ops as ring, 6 F2 vs 9 F2
// state per row-half). 4-stage cp.async ring (73.7KB dyn smem), depth-3,
// wait_group 2, f32x2 math, single launch + last-block reduction.
// Shapes fixed: (B=4, C=4, D=64, H=128, W=128), fp32, out = 1 float.

#define D_DIM 64
#define H_DIM 128
#define W_DIM 128
#define HW    (H_DIM * W_DIM)
#define TH 16
#define PR 18
#define ZC 16
#define NP 18                    // planes touched per block
#define NSTAGE 4
#define PLANE_F4 1152            // (P,T) * 18 rows * 32 f4
#define TOFF 576                 // f4 offset of T tile within stage
#define STAGE_BYTES (PLANE_F4 * 16)       // 18432
#define DSM_BYTES (NSTAGE * STAGE_BYTES)  // 73728
#define NBLK 512

typedef unsigned long long F2;   // packed f32x2

__device__ __forceinline__ F2 PACK2(float lo, float hi) {
    F2 r; asm("mov.b64 %0,{%1,%2};" : "=l"(r) : "f"(lo), "f"(hi)); return r;
}
__device__ __forceinline__ void UNPACK2(F2 v, float& lo, float& hi) {
    asm("mov.b64 {%0,%1},%2;" : "=f"(lo), "=f"(hi) : "l"(v));
}
__device__ __forceinline__ F2 ADD2(F2 a, F2 b) {
    F2 r; asm("add.rn.f32x2 %0,%1,%2;" : "=l"(r) : "l"(a), "l"(b)); return r;
}
__device__ __forceinline__ F2 SUB2(F2 a, F2 b) {
    F2 r; asm("sub.rn.f32x2 %0,%1,%2;" : "=l"(r) : "l"(a), "l"(b)); return r;
}
__device__ __forceinline__ F2 FMA2(F2 a, F2 b, F2 c) {
    F2 r; asm("fma.rn.f32x2 %0,%1,%2,%3;" : "=l"(r) : "l"(a), "l"(b), "l"(c)); return r;
}
__device__ __forceinline__ F2 ABS2(F2 a) { return a & 0x7FFFFFFF7FFFFFFFULL; }

__device__ __forceinline__ void cpasync16(uint32_t dst, const float* src, int sz) {
    asm volatile("cp.async.cg.shared.global [%0], [%1], 16, %2;\n"
                 :: "r"(dst), "l"(src), "r"(sz) : "memory");
}
__device__ __forceinline__ void cp_commit() {
    asm volatile("cp.async.commit_group;\n" ::: "memory");
}
__device__ __forceinline__ void cp_wait2() {
    asm volatile("cp.async.wait_group 2;\n" ::: "memory");
}

extern __shared__ float4 dsm[];
__shared__ float wsum_sm[8];

__device__ float g_partials[NBLK];
__device__ unsigned g_count = 0;

// w-stage: smooth (+ optional deriv) along w on a packed 4-float row segment.
template<bool WANT_D>
__device__ __forceinline__ void wstage(F2 a0, F2 a1, F2 TWO2, bool l0, bool l31,
                                       F2& s0, F2& s1, F2& d0, F2& d1) {
    float x0, x1, x2, x3;
    UNPACK2(a0, x0, x1);
    UNPACK2(a1, x2, x3);
    float xL = __shfl_up_sync(0xffffffffu, x3, 1);
    float xR = __shfl_down_sync(0xffffffffu, x0, 1);
    if (l0)  xL = 0.f;
    if (l31) xR = 0.f;
    F2 pm  = PACK2(xL, x0);
    F2 p12 = PACK2(x1, x2);
    F2 pr  = PACK2(x3, xR);
    s0 = ADD2(FMA2(a0, TWO2, pm),  p12);
    s1 = ADD2(FMA2(a1, TWO2, p12), pr);
    if (WANT_D) {
        d0 = SUB2(p12, pm);
        d1 = SUB2(pr, p12);
    }
}

// Consume plane from stage STG: outputs S (ss), Dh (ds), Dw (sd) for the
// warp's TWO output rows (2w, 2w+1), each split into 2 packed halves.
template<int STG>
__device__ __forceinline__ void plane_consume(int warp, int lane,
                                              F2 (*S)[2], F2 (*Dh)[2], F2 (*Dw)[2],
                                              F2 TWO2, bool l0, bool l31) {
    const ulonglong2* sb =
        reinterpret_cast<const ulonglong2*>(dsm) + STG * PLANE_F4 / 2 * 0 + STG * (PLANE_F4 / 2);
    // NOTE: PLANE_F4 f4 = PLANE_F4/2 ulonglong2? No: one float4 == one ulonglong2.
    // Recompute cleanly:
    const ulonglong2* sbase =
        reinterpret_cast<const ulonglong2*>(dsm) + (size_t)STG * PLANE_F4;
    F2 e[4][2];
#pragma unroll
    for (int dr = 0; dr < 4; ++dr) {
        ulonglong2 pv = sbase[(2 * warp + dr) * 32 + lane];
        ulonglong2 tv = sbase[TOFF + (2 * warp + dr) * 32 + lane];
        e[dr][0] = SUB2(pv.x, tv.x);
        e[dr][1] = SUB2(pv.y, tv.y);
    }
#pragma unroll
    for (int r = 0; r < 2; ++r) {
        F2 hs0 = ADD2(FMA2(e[r + 1][0], TWO2, e[r][0]), e[r + 2][0]);
        F2 hs1 = ADD2(FMA2(e[r + 1][1], TWO2, e[r][1]), e[r + 2][1]);
        F2 hd0 = SUB2(e[r + 2][0], e[r][0]);
        F2 hd1 = SUB2(e[r + 2][1], e[r][1]);
        wstage<true>(hs0, hs1, TWO2, l0, l31, S[r][0], S[r][1], Dw[r][0], Dw[r][1]);
        F2 dummy0, dummy1;
        wstage<false>(hd0, hd1, TWO2, l0, l31, Dh[r][0], Dh[r][1], dummy0, dummy1);
    }
    (void)sb;
}

__global__ __launch_bounds__(256, 2)
void sg3d_loss_kernel(const float* __restrict__ pred,
                      const float* __restrict__ tgt,
                      float* __restrict__ out) {
    const int tid  = threadIdx.x;
    const int lane = tid & 31;
    const int warp = tid >> 5;          // 0..7 -> output rows 2w, 2w+1
    const bool l0  = (lane == 0);
    const bool l31 = (lane == 31);

    const int h0 = blockIdx.x * TH;
    const int bc = blockIdx.y;
    const int z0 = blockIdx.z * ZC;
    const int bid = blockIdx.x + (blockIdx.y << 3) + (blockIdx.z << 7);

    const size_t base = (size_t)bc * D_DIM * HW;
    const float* P = pred + base;
    const float* T = tgt + base;

    uint32_t smem_base;
    asm("{ .reg .u64 t; cvta.to.shared.u64 t, %1; cvt.u32.u64 %0, t; }"
        : "=r"(smem_base) : "l"((const void*)&dsm[0]));

    // ---- per-slot hoisted params; slot k covers idx = tid + 256k (<1152) ----
    const float* gp[5];
    int szb[5];
    const uint32_t saddr0 = smem_base + (uint32_t)tid * 16u;
    const bool act4 = (tid < 128);
#pragma unroll
    for (int k = 0; k < 5; ++k) {
        int idx = tid + 256 * k;
        if (idx >= PLANE_F4) idx = PLANE_F4 - 1;    // inert (slot4, tid>=128)
        int a   = idx >= TOFF;                      // 0=P tile, 1=T tile
        int rel = idx - a * TOFF;
        int row = rel >> 5;                         // 0..17
        int c4  = rel & 31;
        int gh  = h0 - 1 + row;
        int rowok = (unsigned)gh < (unsigned)H_DIM;
        int soff = (rowok ? gh : 0) * W_DIM + c4 * 4;
        gp[k] = (a ? T : P) + (ptrdiff_t)(z0 - 1) * HW + soff;
        szb[k] = rowok ? 16 : 0;
    }
    const int zf_ok = (z0 > 0);
    const int zl_ok = (z0 + ZC < D_DIM);

#define ISSUE_PLANE(STAGE, OK)                                                \
    do {                                                                      \
        int m_ = (OK) ? ~0 : 0;                                               \
        cpasync16(saddr0 +          (STAGE) * STAGE_BYTES, gp[0], szb[0] & m_); \
        cpasync16(saddr0 + 4096u  + (STAGE) * STAGE_BYTES, gp[1], szb[1] & m_); \
        cpasync16(saddr0 + 8192u  + (STAGE) * STAGE_BYTES, gp[2], szb[2] & m_); \
        cpasync16(saddr0 + 12288u + (STAGE) * STAGE_BYTES, gp[3], szb[3] & m_); \
        if (act4)                                                             \
            cpasync16(saddr0 + 16384u + (STAGE) * STAGE_BYTES, gp[4],         \
                      szb[4] & m_);                                           \
        gp[0] += HW; gp[1] += HW; gp[2] += HW; gp[3] += HW; gp[4] += HW;      \
    } while (0)

    const F2 TWO2 = 0x4000000040000000ULL;

    // pend-style z-state per (row, half): S history (2) + pend/last for Dh,Dw
    F2 s1[2][2] = {{0,0},{0,0}}, s2[2][2] = {{0,0},{0,0}};
    F2 ph[2][2] = {{0,0},{0,0}}, dh1[2][2] = {{0,0},{0,0}};
    F2 pw[2][2] = {{0,0},{0,0}}, dw1[2][2] = {{0,0},{0,0}};
    F2 acc[2] = {0ULL, 0ULL};

    // prologue: planes 0,1,2 -> stages 0,1,2
    ISSUE_PLANE(0, zf_ok); cp_commit();
    ISSUE_PLANE(1, 1);     cp_commit();
    ISSUE_PLANE(2, 1);     cp_commit();

#define STEP(I)                                                               \
    do {                                                                      \
        cp_wait2();                                                           \
        __syncthreads();                                                      \
        if ((I) + 3 < NP)                                                     \
            ISSUE_PLANE(((I) + 3) % NSTAGE,                                   \
                        (((I) + 3) == NP - 1) ? zl_ok : 1);                   \
        cp_commit();                                                          \
        F2 S[2][2], Dh[2][2], Dw[2][2];                                       \
        plane_consume<(I) % NSTAGE>(warp, lane, S, Dh, Dw, TWO2, l0, l31);    \
        if ((I) >= 2) {                                                       \
            _Pragma("unroll")                                                 \
            for (int r = 0; r < 2; ++r) {                                     \
                _Pragma("unroll")                                             \
                for (int h = 0; h < 2; ++h) {                                 \
                    F2 gd = SUB2(S[r][h], s2[r][h]);                          \
                    F2 gh_ = ADD2(ph[r][h], Dh[r][h]);                        \
                    F2 gw_ = ADD2(pw[r][h], Dw[r][h]);                        \
                    acc[h] = ADD2(acc[h], ABS2(gd));                          \
                    acc[h] = ADD2(acc[h], ABS2(gh_));                         \
                    acc[h] = ADD2(acc[h], ABS2(gw_));                         \
                }                                                             \
            }                                                                 \
        }                                                                     \
        _Pragma("unroll")                                                     \
        for (int r = 0; r < 2; ++r) {                                         \
            _Pragma("unroll")                                                 \
            for (int h = 0; h < 2; ++h) {                                     \
                ph[r][h]  = FMA2(Dh[r][h], TWO2, dh1[r][h]);                  \
                dh1[r][h] = Dh[r][h];                                         \
                pw[r][h]  = FMA2(Dw[r][h], TWO2, dw1[r][h]);                  \
                dw1[r][h] = Dw[r][h];                                         \
                s2[r][h]  = s1[r][h];                                         \
                s1[r][h]  = S[r][h];                                          \
            }                                                                 \
        }                                                                     \
    } while (0)

    STEP(0);  STEP(1);  STEP(2);  STEP(3);  STEP(4);  STEP(5);
    STEP(6);  STEP(7);  STEP(8);  STEP(9);  STEP(10); STEP(11);
    STEP(12); STEP(13); STEP(14); STEP(15); STEP(16); STEP(17);

    // ---- block reduction ----
    float ax, ay, az, aw;
    UNPACK2(acc[0], ax, ay);
    UNPACK2(acc[1], az, aw);
    float a = (ax + ay) + (az + aw);
#pragma unroll
    for (int off = 16; off > 0; off >>= 1)
        a += __shfl_down_sync(0xffffffffu, a, off);

    if (lane == 0) wsum_sm[warp] = a;
    __syncthreads();

    __shared__ bool is_last;
    if (tid == 0) {
        float v = 0.f;
#pragma unroll
        for (int w = 0; w < 8; ++w) v += wsum_sm[w];
        g_partials[bid] = v;
        __threadfence();
        unsigned old = atomicAdd(&g_count, 1u);
        is_last = (old == NBLK - 1);
    }
    __syncthreads();

    if (is_last) {
        __threadfence();
        const volatile float* pv = g_partials;
        float s = 0.f;
#pragma unroll
        for (int k = 0; k < NBLK / 256; ++k)
            s += pv[tid + 256 * k];
#pragma unroll
        for (int off = 16; off > 0; off >>= 1)
            s += __shfl_down_sync(0xffffffffu, s, off);
        if (lane == 0) wsum_sm[warp] = s;
        __syncthreads();
        if (tid == 0) {
            float v = 0.f;
#pragma unroll
            for (int w = 0; w < 8; ++w) v += wsum_sm[w];
            out[0] = v * (1.0f / (3.0f * 16.0f * 64.0f * 128.0f * 128.0f));
            g_count = 0;            // reset for next graph replay
        }
    }
}

extern "C" void kernel_launch(void* const* d_in, const int* in_sizes, int n_in,
                              void* d_out, int out_size) {
    const float* pred = (const float*)d_in[0];
    const float* tgt  = (const float*)d_in[1];
    float* out = (float*)d_out;

    cudaFuncSetAttribute(sg3d_loss_kernel,
                         cudaFuncAttributeMaxDynamicSharedMemorySize, DSM_BYTES);

    dim3 grid(H_DIM / TH, 16, D_DIM / ZC);   // 8 x 16 x 4 = 512 blocks
    sg3d_loss_kernel<<<grid, 256, DSM_BYTES>>>(pred, tgt, out);
}